// round 1
// baseline (speedup 1.0000x reference)
#include <cuda_runtime.h>

#define SEQN 4096
#define DM   1024
#define NH   16
#define DK   64

// Scratch (device globals — no runtime allocation allowed)
__device__ float g_Q[SEQN * DM];
__device__ float g_K[SEQN * DM];
__device__ float g_V[SEQN * DM];
__device__ float g_X[SEQN * DM];

// ---------------------------------------------------------------------------
// GEMM with bias: C[M,N] = A[M,K] @ W[N,K]^T + b,  M=4096, N=1024, K=1024.
// 64x64 block tile, BK=16, 256 threads, 4x4 per thread, float4 everywhere.
// A and W tiles stored k-major (transposed) in smem for contiguous inner reads.
// ---------------------------------------------------------------------------
__global__ __launch_bounds__(256) void gemm_bias(
    const float* __restrict__ A, const float* __restrict__ W,
    const float* __restrict__ b, float* __restrict__ C)
{
    __shared__ float Ast[16][68];
    __shared__ float Wst[16][68];

    const int tid = threadIdx.x;
    const int tx = tid & 15, ty = tid >> 4;
    const int bm = blockIdx.y << 6, bn = blockIdx.x << 6;
    const int lr = tid >> 2;            // 0..63 tile row
    const int lk = (tid & 3) << 2;      // 0,4,8,12 k-group

    const float* Ap = A + (size_t)(bm + lr) * DM + lk;
    const float* Wp = W + (size_t)(bn + lr) * DM + lk;

    float acc[4][4] = {};

    for (int k0 = 0; k0 < DM; k0 += 16) {
        const float4 av = *(const float4*)(Ap + k0);
        const float4 wv = *(const float4*)(Wp + k0);
        __syncthreads();
        Ast[lk + 0][lr] = av.x; Ast[lk + 1][lr] = av.y;
        Ast[lk + 2][lr] = av.z; Ast[lk + 3][lr] = av.w;
        Wst[lk + 0][lr] = wv.x; Wst[lk + 1][lr] = wv.y;
        Wst[lk + 2][lr] = wv.z; Wst[lk + 3][lr] = wv.w;
        __syncthreads();

        #pragma unroll
        for (int k = 0; k < 16; k++) {
            const float4 a = *(const float4*)&Ast[k][ty << 2];
            const float4 w = *(const float4*)&Wst[k][tx << 2];
            const float ar[4] = {a.x, a.y, a.z, a.w};
            const float wr[4] = {w.x, w.y, w.z, w.w};
            #pragma unroll
            for (int i = 0; i < 4; i++)
                #pragma unroll
                for (int j = 0; j < 4; j++)
                    acc[i][j] = fmaf(ar[i], wr[j], acc[i][j]);
        }
    }

    const float4 bb = *(const float4*)&b[bn + (tx << 2)];
    #pragma unroll
    for (int i = 0; i < 4; i++) {
        float4 o;
        o.x = acc[i][0] + bb.x; o.y = acc[i][1] + bb.y;
        o.z = acc[i][2] + bb.z; o.w = acc[i][3] + bb.w;
        *(float4*)&C[(size_t)(bm + (ty << 2) + i) * DM + bn + (tx << 2)] = o;
    }
}

// ---------------------------------------------------------------------------
// Flash attention, fp32. Grid: (SEQ/64, H). 256 threads, 4x4 register tiles.
// Qs/KVs: d-major (transposed) with XOR swizzle -> conflict-free loads+stores,
// no padding (3 x 16 KB = exactly 48 KB static smem).
// Softmax lives in registers: each score row is owned by 16 consecutive lanes,
// reduced with shfl_xor (width<=8 xor stays in the 16-lane half).
// ---------------------------------------------------------------------------
__global__ __launch_bounds__(256) void flash_attn(
    const float* __restrict__ Q, const float* __restrict__ K,
    const float* __restrict__ V, float* __restrict__ X)
{
    __shared__ float Qs[64 * 64];   // transposed+swizzled
    __shared__ float KVs[64 * 64];  // K: transposed+swizzled; later V: natural
    __shared__ float Ps[64 * 64];   // P row-major

    const int tid = threadIdx.x;
    const int tx = tid & 15, ty = tid >> 4;
    const int h = blockIdx.y;
    const int q0 = blockIdx.x << 6;
    const int col0 = h * DK;

    // Load Q tile, pre-scaled by 1/sqrt(64), transposed + swizzled.
    {
        const int r = tid >> 2;
        const int dg0 = tid & 3;
        #pragma unroll
        for (int rep = 0; rep < 4; rep++) {
            const int dg = dg0 + (rep << 2);
            const float4 v = *(const float4*)&Q[(size_t)(q0 + r) * DM + col0 + (dg << 2)];
            const float vv[4] = {v.x, v.y, v.z, v.w};
            #pragma unroll
            for (int i = 0; i < 4; i++) {
                const int d = (dg << 2) + i;
                Qs[(d << 6) + ((((r >> 2) ^ (d & 15)) << 2) | (r & 3))] = vv[i] * 0.125f;
            }
        }
    }

    float acc[4][4] = {};
    float mreg[4] = {-1e30f, -1e30f, -1e30f, -1e30f};
    float lreg[4] = {0.f, 0.f, 0.f, 0.f};

    for (int n0 = 0; n0 < SEQN; n0 += 64) {
        __syncthreads();   // previous iteration's PV readers done with KVs
        // Load K tile, transposed + swizzled.
        {
            const int r = tid >> 2;
            const int dg0 = tid & 3;
            #pragma unroll
            for (int rep = 0; rep < 4; rep++) {
                const int dg = dg0 + (rep << 2);
                const float4 v = *(const float4*)&K[(size_t)(n0 + r) * DM + col0 + (dg << 2)];
                const float vv[4] = {v.x, v.y, v.z, v.w};
                #pragma unroll
                for (int i = 0; i < 4; i++) {
                    const int d = (dg << 2) + i;
                    KVs[(d << 6) + ((((r >> 2) ^ (d & 15)) << 2) | (r & 3))] = vv[i];
                }
            }
        }
        __syncthreads();

        // S = (Q * scale) @ K^T  (4x4 per thread; rows ty*4+i, kv cols tx*4+j)
        float s[4][4] = {};
        #pragma unroll 16
        for (int d = 0; d < 64; d++) {
            const float4 qa = *(const float4*)&Qs[(d << 6) + ((ty ^ (d & 15)) << 2)];
            const float4 kb = *(const float4*)&KVs[(d << 6) + ((tx ^ (d & 15)) << 2)];
            const float qr[4] = {qa.x, qa.y, qa.z, qa.w};
            const float kr[4] = {kb.x, kb.y, kb.z, kb.w};
            #pragma unroll
            for (int i = 0; i < 4; i++)
                #pragma unroll
                for (int j = 0; j < 4; j++)
                    s[i][j] = fmaf(qr[i], kr[j], s[i][j]);
        }

        // Online softmax in registers (row spread over 16 lanes).
        #pragma unroll
        for (int i = 0; i < 4; i++) {
            float tmax = fmaxf(fmaxf(s[i][0], s[i][1]), fmaxf(s[i][2], s[i][3]));
            #pragma unroll
            for (int off = 8; off > 0; off >>= 1)
                tmax = fmaxf(tmax, __shfl_xor_sync(0xffffffffu, tmax, off, 32));
            const float mnew = fmaxf(mreg[i], tmax);
            const float c = __expf(mreg[i] - mnew);
            mreg[i] = mnew;
            float tsum = 0.f;
            #pragma unroll
            for (int j = 0; j < 4; j++) {
                s[i][j] = __expf(s[i][j] - mnew);
                tsum += s[i][j];
            }
            #pragma unroll
            for (int off = 8; off > 0; off >>= 1)
                tsum += __shfl_xor_sync(0xffffffffu, tsum, off, 32);
            lreg[i] = lreg[i] * c + tsum;
            #pragma unroll
            for (int j = 0; j < 4; j++) acc[i][j] *= c;
            *(float4*)&Ps[(((ty << 2) + i) << 6) + (tx << 2)] =
                make_float4(s[i][0], s[i][1], s[i][2], s[i][3]);
        }
        __syncthreads();   // P visible; S-gemm done reading KVs

        // Load V tile (natural layout).
        {
            const int r = tid >> 2;
            const int dg0 = tid & 3;
            #pragma unroll
            for (int rep = 0; rep < 4; rep++) {
                const int dg = dg0 + (rep << 2);
                const float4 v = *(const float4*)&V[(size_t)(n0 + r) * DM + col0 + (dg << 2)];
                *(float4*)&KVs[(r << 6) + (dg << 2)] = v;
            }
        }
        __syncthreads();

        // O += P @ V
        #pragma unroll 8
        for (int n4 = 0; n4 < 64; n4 += 4) {
            float pr[4][4];
            #pragma unroll
            for (int i = 0; i < 4; i++) {
                const float4 t = *(const float4*)&Ps[(((ty << 2) + i) << 6) + n4];
                pr[i][0] = t.x; pr[i][1] = t.y; pr[i][2] = t.z; pr[i][3] = t.w;
            }
            #pragma unroll
            for (int k = 0; k < 4; k++) {
                const float4 vv = *(const float4*)&KVs[((n4 + k) << 6) + (tx << 2)];
                const float vr[4] = {vv.x, vv.y, vv.z, vv.w};
                #pragma unroll
                for (int i = 0; i < 4; i++)
                    #pragma unroll
                    for (int j = 0; j < 4; j++)
                        acc[i][j] = fmaf(pr[i][k], vr[j], acc[i][j]);
            }
        }
    }

    // Epilogue: normalize and write to X[s, h*64 + d].
    #pragma unroll
    for (int i = 0; i < 4; i++) {
        const float inv = 1.0f / lreg[i];
        float4 o;
        o.x = acc[i][0] * inv; o.y = acc[i][1] * inv;
        o.z = acc[i][2] * inv; o.w = acc[i][3] * inv;
        *(float4*)&X[(size_t)(q0 + (ty << 2) + i) * DM + col0 + (tx << 2)] = o;
    }
}

// ---------------------------------------------------------------------------
extern "C" void kernel_launch(void* const* d_in, const int* in_sizes, int n_in,
                              void* d_out, int out_size)
{
    const float* query = (const float*)d_in[0];
    const float* key   = (const float*)d_in[1];
    const float* value = (const float*)d_in[2];
    const float* Wq    = (const float*)d_in[3];
    const float* bq    = (const float*)d_in[4];
    const float* Wk    = (const float*)d_in[5];
    const float* bk    = (const float*)d_in[6];
    const float* Wv    = (const float*)d_in[7];
    const float* bv    = (const float*)d_in[8];
    const float* Wo    = (const float*)d_in[9];
    const float* bo    = (const float*)d_in[10];
    float* out = (float*)d_out;

    float *Qp, *Kp, *Vp, *Xp;
    cudaGetSymbolAddress((void**)&Qp, g_Q);
    cudaGetSymbolAddress((void**)&Kp, g_K);
    cudaGetSymbolAddress((void**)&Vp, g_V);
    cudaGetSymbolAddress((void**)&Xp, g_X);

    const dim3 gg(DM / 64, SEQN / 64);   // (16, 64)
    gemm_bias<<<gg, 256>>>(query, Wq, bq, Qp);
    gemm_bias<<<gg, 256>>>(key,   Wk, bk, Kp);
    gemm_bias<<<gg, 256>>>(value, Wv, bv, Vp);
    flash_attn<<<dim3(SEQN / 64, NH), 256>>>(Qp, Kp, Vp, Xp);
    gemm_bias<<<gg, 256>>>(Xp, Wo, bo, out);
}

// round 7
// speedup vs baseline: 2.4395x; 2.4395x over previous
#include <cuda_runtime.h>
#include <cstdint>

#define SEQN 4096
#define DM   1024
#define NH   16
#define DK   64

// Scratch (device globals — no runtime allocation allowed)
__device__ float g_Q[SEQN * DM];
__device__ float g_K[SEQN * DM];
__device__ float g_V[SEQN * DM];
__device__ float g_X[SEQN * DM];

__device__ __forceinline__ uint32_t f2tf32(float x) {
    uint32_t u;
    asm("cvt.rna.tf32.f32 %0, %1;" : "=r"(u) : "f"(x));
    return u;
}
// D = A@B + D, A 16x8 tf32 row-major, B 8x8 tf32 col-major, D fp32.
__device__ __forceinline__ void mma_tf32(float c[4], const uint32_t a[4], const uint32_t b[2]) {
    asm volatile(
        "mma.sync.aligned.m16n8k8.row.col.f32.tf32.tf32.f32 "
        "{%0,%1,%2,%3}, {%4,%5,%6,%7}, {%8,%9}, {%0,%1,%2,%3};"
        : "+f"(c[0]), "+f"(c[1]), "+f"(c[2]), "+f"(c[3])
        : "r"(a[0]), "r"(a[1]), "r"(a[2]), "r"(a[3]), "r"(b[0]), "r"(b[1]));
}

// ===========================================================================
// GEMM: C[M,N] = A[M,K] @ W[N,K]^T + b.  M=4096, N=K=1024, tf32 mma.sync.
// CTA 128x128, K-block 32, 8 warps in 4(M)x2(N), warp tile 32x64.
// Smem rows padded to 36 floats -> fragment loads conflict-free.
// ===========================================================================
#define GLDA 36
__global__ __launch_bounds__(256) void gemm_tc(
    const float* __restrict__ A, const float* __restrict__ W,
    const float* __restrict__ bias, float* __restrict__ C)
{
    __shared__ uint32_t As[128 * GLDA];
    __shared__ uint32_t Ws[128 * GLDA];

    const int tid = threadIdx.x;
    const int wid = tid >> 5, lane = tid & 31;
    const int wm = wid & 3, wn = wid >> 2;          // warp coords
    const int lr = lane >> 2, lc = lane & 3;        // frag row/col within tile
    const int bm = blockIdx.y << 7, bn = blockIdx.x << 7;

    float acc[2][8][4];
    #pragma unroll
    for (int i = 0; i < 2; i++)
        #pragma unroll
        for (int j = 0; j < 8; j++)
            #pragma unroll
            for (int q = 0; q < 4; q++) acc[i][j][q] = 0.f;

    for (int kb = 0; kb < 32; kb++) {
        __syncthreads();
        // Stage A/W K-block: 128 rows x 32 cols each, tf32-rounded.
        #pragma unroll
        for (int r = 0; r < 4; r++) {
            const int idx = tid + (r << 8);
            const int row = idx >> 3, f4 = idx & 7;
            const size_t g = (size_t)row * DM + (kb << 5) + (f4 << 2);
            const float4 av = *(const float4*)&A[(size_t)bm * DM + g];
            const float4 wv = *(const float4*)&W[(size_t)bn * DM + g];
            uint4 at, wt;
            at.x = f2tf32(av.x); at.y = f2tf32(av.y); at.z = f2tf32(av.z); at.w = f2tf32(av.w);
            wt.x = f2tf32(wv.x); wt.y = f2tf32(wv.y); wt.z = f2tf32(wv.z); wt.w = f2tf32(wv.w);
            *(uint4*)&As[row * GLDA + (f4 << 2)] = at;
            *(uint4*)&Ws[row * GLDA + (f4 << 2)] = wt;
        }
        __syncthreads();

        #pragma unroll
        for (int ks = 0; ks < 4; ks++) {
            const int ck = (ks << 3) + lc;
            uint32_t af[2][4];
            #pragma unroll
            for (int i = 0; i < 2; i++) {
                const int rb = (wm << 5) + (i << 4) + lr;
                af[i][0] = As[rb * GLDA + ck];
                af[i][1] = As[(rb + 8) * GLDA + ck];
                af[i][2] = As[rb * GLDA + ck + 4];
                af[i][3] = As[(rb + 8) * GLDA + ck + 4];
            }
            #pragma unroll
            for (int j = 0; j < 8; j++) {
                const int nb = (wn << 6) + (j << 3) + lr;
                uint32_t bf[2];
                bf[0] = Ws[nb * GLDA + ck];
                bf[1] = Ws[nb * GLDA + ck + 4];
                mma_tf32(acc[0][j], af[0], bf);
                mma_tf32(acc[1][j], af[1], bf);
            }
        }
    }

    // Epilogue: rows 32wm+16i+lr(+8), cols 64wn+8j+2lc(+1), add bias.
    #pragma unroll
    for (int i = 0; i < 2; i++) {
        const int r0 = bm + (wm << 5) + (i << 4) + lr;
        #pragma unroll
        for (int j = 0; j < 8; j++) {
            const int c0 = bn + (wn << 6) + (j << 3) + (lc << 1);
            const float b0 = bias[c0], b1 = bias[c0 + 1];
            float2 o;
            o.x = acc[i][j][0] + b0; o.y = acc[i][j][1] + b1;
            *(float2*)&C[(size_t)r0 * DM + c0] = o;
            o.x = acc[i][j][2] + b0; o.y = acc[i][j][3] + b1;
            *(float2*)&C[(size_t)(r0 + 8) * DM + c0] = o;
        }
    }
}

// ===========================================================================
// Flash attention, tf32 mma.sync. Grid (SEQ/128, H), 256 threads.
// Warp w owns q-rows 16w..16w+15 for ALL 64 kv cols of the tile -> softmax
// rows never cross warps (shfl_xor 1,2 within 4-lane quad).
// Q fragments preloaded to registers (S-gemm A needs no LDS).
// Smem (dynamic, floats, stride 68): P[128] | K[64] | Vt[64].
// ===========================================================================
#define FLDA 68
#define PS_OFF 0
#define KS_OFF (128 * FLDA)                 // 8704
#define VT_OFF (KS_OFF + 64 * FLDA)         // 13056
#define FA_SMEM ((VT_OFF + 64 * FLDA) * 4)  // 69632 bytes

__global__ __launch_bounds__(256, 1) void flash_attn_tc(
    const float* __restrict__ Q, const float* __restrict__ K,
    const float* __restrict__ V, float* __restrict__ X)
{
    extern __shared__ uint32_t smf[];
    uint32_t* Ps = smf + PS_OFF;
    uint32_t* Ks = smf + KS_OFF;
    uint32_t* Vt = smf + VT_OFF;

    const int tid = threadIdx.x;
    const int wid = tid >> 5, lane = tid & 31;
    const int lr = lane >> 2, lc = lane & 3;
    const int h = blockIdx.y;
    const int q0 = blockIdx.x << 7;
    const int col0 = h * DK;

    // ---- Stage Q (scaled) into Ps region, then preload fragments ----
    #pragma unroll
    for (int r = 0; r < 8; r++) {
        const int idx = tid + (r << 8);
        const int row = idx >> 4, f4 = idx & 15;
        const float4 v = *(const float4*)&Q[(size_t)(q0 + row) * DM + col0 + (f4 << 2)];
        uint4 t;
        t.x = f2tf32(v.x * 0.125f); t.y = f2tf32(v.y * 0.125f);
        t.z = f2tf32(v.z * 0.125f); t.w = f2tf32(v.w * 0.125f);
        *(uint4*)&Ps[row * FLDA + (f4 << 2)] = t;
    }
    __syncthreads();
    uint32_t qf[8][4];
    {
        const int rb = (wid << 4) + lr;
        #pragma unroll
        for (int ks = 0; ks < 8; ks++) {
            const int ck = (ks << 3) + lc;
            qf[ks][0] = Ps[rb * FLDA + ck];
            qf[ks][1] = Ps[(rb + 8) * FLDA + ck];
            qf[ks][2] = Ps[rb * FLDA + ck + 4];
            qf[ks][3] = Ps[(rb + 8) * FLDA + ck + 4];
        }
    }

    float of[8][4];
    #pragma unroll
    for (int j = 0; j < 8; j++)
        #pragma unroll
        for (int q = 0; q < 4; q++) of[j][q] = 0.f;
    float m0 = -1e30f, m1 = -1e30f, l0 = 0.f, l1 = 0.f;

    for (int t = 0; t < SEQN / 64; t++) {
        const int n0 = t << 6;
        __syncthreads();   // previous PV done with Ks/Vt/Ps
        // ---- Stage K tile [64 kv][64 d] row-major ----
        #pragma unroll
        for (int r = 0; r < 4; r++) {
            const int idx = tid + (r << 8);
            const int row = idx >> 4, f4 = idx & 15;
            const float4 v = *(const float4*)&K[(size_t)(n0 + row) * DM + col0 + (f4 << 2)];
            uint4 w;
            w.x = f2tf32(v.x); w.y = f2tf32(v.y); w.z = f2tf32(v.z); w.w = f2tf32(v.w);
            *(uint4*)&Ks[row * FLDA + (f4 << 2)] = w;
        }
        // ---- Stage Vt [64 d][64 kv] (transpose of V tile) ----
        #pragma unroll
        for (int r = 0; r < 4; r++) {
            const int idx = tid + (r << 8);
            const int kv = idx & 63, d4 = idx >> 6;
            const float4 v = *(const float4*)&V[(size_t)(n0 + kv) * DM + col0 + (d4 << 2)];
            Vt[((d4 << 2) + 0) * FLDA + kv] = f2tf32(v.x);
            Vt[((d4 << 2) + 1) * FLDA + kv] = f2tf32(v.y);
            Vt[((d4 << 2) + 2) * FLDA + kv] = f2tf32(v.z);
            Vt[((d4 << 2) + 3) * FLDA + kv] = f2tf32(v.w);
        }
        __syncthreads();

        // ---- S = Qs @ K^T : warp rows 16w..+15, cols 0..63 ----
        float sc[8][4];
        #pragma unroll
        for (int j = 0; j < 8; j++)
            #pragma unroll
            for (int q = 0; q < 4; q++) sc[j][q] = 0.f;
        #pragma unroll
        for (int ks = 0; ks < 8; ks++) {
            const int ck = (ks << 3) + lc;
            #pragma unroll
            for (int j = 0; j < 8; j++) {
                const int nb = (j << 3) + lr;
                uint32_t bf[2];
                bf[0] = Ks[nb * FLDA + ck];
                bf[1] = Ks[nb * FLDA + ck + 4];
                mma_tf32(sc[j], qf[ks], bf);
            }
        }

        // ---- Online softmax: rows lr (c0,c1) and lr+8 (c2,c3) ----
        float mx0 = -1e30f, mx1 = -1e30f;
        #pragma unroll
        for (int j = 0; j < 8; j++) {
            mx0 = fmaxf(mx0, fmaxf(sc[j][0], sc[j][1]));
            mx1 = fmaxf(mx1, fmaxf(sc[j][2], sc[j][3]));
        }
        mx0 = fmaxf(mx0, __shfl_xor_sync(0xffffffffu, mx0, 1));
        mx0 = fmaxf(mx0, __shfl_xor_sync(0xffffffffu, mx0, 2));
        mx1 = fmaxf(mx1, __shfl_xor_sync(0xffffffffu, mx1, 1));
        mx1 = fmaxf(mx1, __shfl_xor_sync(0xffffffffu, mx1, 2));
        const float m0n = fmaxf(m0, mx0), m1n = fmaxf(m1, mx1);
        const float c0 = __expf(m0 - m0n), c1 = __expf(m1 - m1n);
        m0 = m0n; m1 = m1n;
        float s0 = 0.f, s1 = 0.f;
        #pragma unroll
        for (int j = 0; j < 8; j++) {
            sc[j][0] = __expf(sc[j][0] - m0n);
            sc[j][1] = __expf(sc[j][1] - m0n);
            sc[j][2] = __expf(sc[j][2] - m1n);
            sc[j][3] = __expf(sc[j][3] - m1n);
            s0 += sc[j][0] + sc[j][1];
            s1 += sc[j][2] + sc[j][3];
        }
        s0 += __shfl_xor_sync(0xffffffffu, s0, 1);
        s0 += __shfl_xor_sync(0xffffffffu, s0, 2);
        s1 += __shfl_xor_sync(0xffffffffu, s1, 1);
        s1 += __shfl_xor_sync(0xffffffffu, s1, 2);
        l0 = l0 * c0 + s0; l1 = l1 * c1 + s1;
        #pragma unroll
        for (int j = 0; j < 8; j++) {
            of[j][0] *= c0; of[j][1] *= c0;
            of[j][2] *= c1; of[j][3] *= c1;
        }
        // ---- P -> smem (tf32), rows 16w+lr / +8, cols 8j+2lc ----
        {
            const int r0 = (wid << 4) + lr;
            #pragma unroll
            for (int j = 0; j < 8; j++) {
                const int cc = (j << 3) + (lc << 1);
                uint2 p0, p1;
                p0.x = f2tf32(sc[j][0]); p0.y = f2tf32(sc[j][1]);
                p1.x = f2tf32(sc[j][2]); p1.y = f2tf32(sc[j][3]);
                *(uint2*)&Ps[r0 * FLDA + cc] = p0;
                *(uint2*)&Ps[(r0 + 8) * FLDA + cc] = p1;
            }
        }
        __syncwarp();   // P writes visible to this warp's frag loads (same rows)

        // ---- O += P @ V : A = Ps rows 16w..+15 (k=kv), B = Vt ----
        #pragma unroll
        for (int ks = 0; ks < 8; ks++) {
            const int ck = (ks << 3) + lc;
            const int rb = (wid << 4) + lr;
            uint32_t af[4];
            af[0] = Ps[rb * FLDA + ck];
            af[1] = Ps[(rb + 8) * FLDA + ck];
            af[2] = Ps[rb * FLDA + ck + 4];
            af[3] = Ps[(rb + 8) * FLDA + ck + 4];
            #pragma unroll
            for (int j = 0; j < 8; j++) {
                const int nb = (j << 3) + lr;
                uint32_t bf[2];
                bf[0] = Vt[nb * FLDA + ck];
                bf[1] = Vt[nb * FLDA + ck + 4];
                mma_tf32(of[j], af, bf);
            }
        }
    }

    // ---- Epilogue: O/l -> X ----
    const float inv0 = 1.0f / l0, inv1 = 1.0f / l1;
    const int r0 = q0 + (wid << 4) + lr;
    #pragma unroll
    for (int j = 0; j < 8; j++) {
        const int cc = col0 + (j << 3) + (lc << 1);
        float2 o;
        o.x = of[j][0] * inv0; o.y = of[j][1] * inv0;
        *(float2*)&X[(size_t)r0 * DM + cc] = o;
        o.x = of[j][2] * inv1; o.y = of[j][3] * inv1;
        *(float2*)&X[(size_t)(r0 + 8) * DM + cc] = o;
    }
}

// ---------------------------------------------------------------------------
extern "C" void kernel_launch(void* const* d_in, const int* in_sizes, int n_in,
                              void* d_out, int out_size)
{
    const float* query = (const float*)d_in[0];
    const float* key   = (const float*)d_in[1];
    const float* value = (const float*)d_in[2];
    const float* Wq    = (const float*)d_in[3];
    const float* bq    = (const float*)d_in[4];
    const float* Wk    = (const float*)d_in[5];
    const float* bk    = (const float*)d_in[6];
    const float* Wv    = (const float*)d_in[7];
    const float* bv    = (const float*)d_in[8];
    const float* Wo    = (const float*)d_in[9];
    const float* bo    = (const float*)d_in[10];
    float* out = (float*)d_out;

    float *Qp, *Kp, *Vp, *Xp;
    cudaGetSymbolAddress((void**)&Qp, g_Q);
    cudaGetSymbolAddress((void**)&Kp, g_K);
    cudaGetSymbolAddress((void**)&Vp, g_V);
    cudaGetSymbolAddress((void**)&Xp, g_X);

    cudaFuncSetAttribute(flash_attn_tc,
                         cudaFuncAttributeMaxDynamicSharedMemorySize, FA_SMEM);

    const dim3 gg(DM / 128, SEQN / 128);   // (8, 32)
    gemm_tc<<<gg, 256>>>(query, Wq, bq, Qp);
    gemm_tc<<<gg, 256>>>(key,   Wk, bk, Kp);
    gemm_tc<<<gg, 256>>>(value, Wv, bv, Vp);
    flash_attn_tc<<<dim3(SEQN / 128, NH), 256, FA_SMEM>>>(Qp, Kp, Vp, Xp);
    gemm_tc<<<gg, 256>>>(Xp, Wo, bo, out);
}

// round 14
// speedup vs baseline: 2.7361x; 1.1216x over previous
#include <cuda_runtime.h>
#include <cstdint>

#define SEQN 4096
#define DM   1024
#define NH   16
#define DK   64

// Scratch (device globals — no runtime allocation allowed)
__device__ float g_Q[SEQN * DM];
__device__ float g_K[SEQN * DM];
__device__ float g_V[SEQN * DM];
__device__ float g_X[SEQN * DM];

__device__ __forceinline__ uint32_t smem_u32(const void* p) {
    uint32_t a;
    asm("{ .reg .u64 t; cvta.to.shared.u64 t, %1; cvt.u32.u64 %0, t; }" : "=r"(a) : "l"(p));
    return a;
}
__device__ __forceinline__ uint32_t f2tf32(float x) {
    uint32_t u;
    asm("cvt.rna.tf32.f32 %0, %1;" : "=r"(u) : "f"(x));
    return u;
}
// D = A@B + D, A 16x8 tf32 row-major, B 8x8 tf32 col-major, D fp32.
__device__ __forceinline__ void mma_tf32(float c[4], const uint32_t a[4], const uint32_t b[2]) {
    asm volatile(
        "mma.sync.aligned.m16n8k8.row.col.f32.tf32.tf32.f32 "
        "{%0,%1,%2,%3}, {%4,%5,%6,%7}, {%8,%9}, {%0,%1,%2,%3};"
        : "+f"(c[0]), "+f"(c[1]), "+f"(c[2]), "+f"(c[3])
        : "r"(a[0]), "r"(a[1]), "r"(a[2]), "r"(a[3]), "r"(b[0]), "r"(b[1]));
}
// b16 ldmatrix on tf32 data: one x4 = a 16(row)x8(b32 col) tile.
// Lane address: row = base + (lane&15), b32 col = +4*(lane>>4).
__device__ __forceinline__ void ldsm_x4(uint32_t r[4], uint32_t addr) {
    asm volatile("ldmatrix.sync.aligned.m8n8.x4.shared.b16 {%0,%1,%2,%3}, [%4];"
        : "=r"(r[0]), "=r"(r[1]), "=r"(r[2]), "=r"(r[3]) : "r"(addr));
}

// ===========================================================================
// GEMM: C[M,N] = A[M,K] @ W[N,K]^T + b.  M=4096, N=K=1024, tf32 mma.sync.
// CTA 128x128, K-block 32, 8 warps 4(M)x2(N), warp tile 32x64.
// ldmatrix fragment loads + register-prefetch double-buffered staging.
// ===========================================================================
#define GLDA 36
__global__ __launch_bounds__(256) void gemm_tc(
    const float* __restrict__ A, const float* __restrict__ W,
    const float* __restrict__ bias, float* __restrict__ C)
{
    __shared__ uint32_t As[128 * GLDA];
    __shared__ uint32_t Ws[128 * GLDA];

    const int tid = threadIdx.x;
    const int wid = tid >> 5, lane = tid & 31;
    const int wm = wid & 3, wn = wid >> 2;
    const int lr = lane >> 2, lc = lane & 3;
    const int lrow = lane & 15, lcol4 = (lane >> 4) << 2;   // ldmatrix lane addr
    const int bm = blockIdx.y << 7, bn = blockIdx.x << 7;

    const uint32_t sAs = smem_u32(As), sWs = smem_u32(Ws);
    const int srow = tid >> 3;            // + 32*r
    const int scg  = (tid & 7) << 2;      // col group

    float acc[2][8][4];
    #pragma unroll
    for (int i = 0; i < 2; i++)
        #pragma unroll
        for (int j = 0; j < 8; j++)
            #pragma unroll
            for (int q = 0; q < 4; q++) acc[i][j][q] = 0.f;

    float4 pa[4], pw[4];
    #pragma unroll
    for (int r = 0; r < 4; r++) {
        const size_t g = (size_t)(srow + (r << 5)) * DM + scg;
        pa[r] = *(const float4*)&A[(size_t)bm * DM + g];
        pw[r] = *(const float4*)&W[(size_t)bn * DM + g];
    }

    for (int kb = 0; kb < 32; kb++) {
        __syncthreads();
        #pragma unroll
        for (int r = 0; r < 4; r++) {
            uint4 at, wt;
            at.x = f2tf32(pa[r].x); at.y = f2tf32(pa[r].y);
            at.z = f2tf32(pa[r].z); at.w = f2tf32(pa[r].w);
            wt.x = f2tf32(pw[r].x); wt.y = f2tf32(pw[r].y);
            wt.z = f2tf32(pw[r].z); wt.w = f2tf32(pw[r].w);
            *(uint4*)&As[(srow + (r << 5)) * GLDA + scg] = at;
            *(uint4*)&Ws[(srow + (r << 5)) * GLDA + scg] = wt;
        }
        if (kb + 1 < 32) {
            #pragma unroll
            for (int r = 0; r < 4; r++) {
                const size_t g = (size_t)(srow + (r << 5)) * DM + ((kb + 1) << 5) + scg;
                pa[r] = *(const float4*)&A[(size_t)bm * DM + g];
                pw[r] = *(const float4*)&W[(size_t)bn * DM + g];
            }
        }
        __syncthreads();

        #pragma unroll
        for (int ks = 0; ks < 4; ks++) {
            const int ck = ks << 3;
            uint32_t a0[4], a1[4];
            const uint32_t aaddr =
                sAs + (uint32_t)((((wm << 5) + lrow) * GLDA + ck + lcol4) << 2);
            ldsm_x4(a0, aaddr);
            ldsm_x4(a1, aaddr + (16 * GLDA << 2));
            #pragma unroll
            for (int jj = 0; jj < 4; jj++) {
                uint32_t b[4];
                const uint32_t baddr =
                    sWs + (uint32_t)((((wn << 6) + (jj << 4) + lrow) * GLDA + ck + lcol4) << 2);
                ldsm_x4(b, baddr);
                uint32_t bf0[2] = {b[0], b[2]}, bf1[2] = {b[1], b[3]};
                mma_tf32(acc[0][(jj << 1) + 0], a0, bf0);
                mma_tf32(acc[1][(jj << 1) + 0], a1, bf0);
                mma_tf32(acc[0][(jj << 1) + 1], a0, bf1);
                mma_tf32(acc[1][(jj << 1) + 1], a1, bf1);
            }
        }
    }

    #pragma unroll
    for (int i = 0; i < 2; i++) {
        const int r0 = bm + (wm << 5) + (i << 4) + lr;
        #pragma unroll
        for (int j = 0; j < 8; j++) {
            const int c0 = bn + (wn << 6) + (j << 3) + (lc << 1);
            const float b0 = bias[c0], b1 = bias[c0 + 1];
            float2 o;
            o.x = acc[i][j][0] + b0; o.y = acc[i][j][1] + b1;
            *(float2*)&C[(size_t)r0 * DM + c0] = o;
            o.x = acc[i][j][2] + b0; o.y = acc[i][j][3] + b1;
            *(float2*)&C[(size_t)(r0 + 8) * DM + c0] = o;
        }
    }
}

// ===========================================================================
// Flash attention, tf32 mma.sync + ldmatrix + prefetched staging.
// Grid (SEQ/128, H), 256 threads; warp owns 16 q-rows for all 64 kv cols.
// Smem (floats, stride 68): P[128] | K[64] | Vt[64].
// ===========================================================================
#define FLDA 68
#define PS_OFF 0
#define KS_OFF (128 * FLDA)
#define VT_OFF (KS_OFF + 64 * FLDA)
#define FA_SMEM ((VT_OFF + 64 * FLDA) * 4)

__global__ __launch_bounds__(256, 1) void flash_attn_tc(
    const float* __restrict__ Q, const float* __restrict__ K,
    const float* __restrict__ V, float* __restrict__ X)
{
    extern __shared__ uint32_t smf[];
    uint32_t* Ps = smf + PS_OFF;
    uint32_t* Ks = smf + KS_OFF;
    uint32_t* Vt = smf + VT_OFF;

    const int tid = threadIdx.x;
    const int wid = tid >> 5, lane = tid & 31;
    const int lr = lane >> 2, lc = lane & 3;
    const int lrow = lane & 15, lcol4 = (lane >> 4) << 2;
    const int h = blockIdx.y;
    const int q0 = blockIdx.x << 7;
    const int col0 = h * DK;

    const uint32_t sPs = smem_u32(Ps), sKs = smem_u32(Ks), sVt = smem_u32(Vt);

    // ---- Stage Q (scaled) into Ps, preload fragments via ldmatrix ----
    {
        const int row0 = tid >> 4, cg = (tid & 15) << 2;
        #pragma unroll
        for (int r = 0; r < 8; r++) {
            const int row = row0 + (r << 4);
            const float4 v = *(const float4*)&Q[(size_t)(q0 + row) * DM + col0 + cg];
            uint4 t;
            t.x = f2tf32(v.x * 0.125f); t.y = f2tf32(v.y * 0.125f);
            t.z = f2tf32(v.z * 0.125f); t.w = f2tf32(v.w * 0.125f);
            *(uint4*)&Ps[row * FLDA + cg] = t;
        }
    }
    __syncthreads();
    uint32_t qf[8][4];
    #pragma unroll
    for (int ks = 0; ks < 8; ks++) {
        const uint32_t qaddr =
            sPs + (uint32_t)((((wid << 4) + lrow) * FLDA + (ks << 3) + lcol4) << 2);
        ldsm_x4(qf[ks], qaddr);
    }

    float of[8][4];
    #pragma unroll
    for (int j = 0; j < 8; j++)
        #pragma unroll
        for (int q = 0; q < 4; q++) of[j][q] = 0.f;
    float m0 = -1e30f, m1 = -1e30f, l0 = 0.f, l1 = 0.f;

    // staging maps
    const int krow0 = tid >> 4, kcg = (tid & 15) << 2;   // K: rows +16r
    const int vkv = tid & 63, vd0 = tid >> 6;            // Vt: d4 +4r

    float4 pk[4], pv[4];
    #pragma unroll
    for (int r = 0; r < 4; r++) {
        pk[r] = *(const float4*)&K[(size_t)(krow0 + (r << 4)) * DM + col0 + kcg];
        pv[r] = *(const float4*)&V[(size_t)vkv * DM + col0 + ((vd0 + (r << 2)) << 2)];
    }

    for (int t = 0; t < SEQN / 64; t++) {
        __syncthreads();   // previous PV done with Ks/Vt/Ps
        #pragma unroll
        for (int r = 0; r < 4; r++) {
            uint4 w;
            w.x = f2tf32(pk[r].x); w.y = f2tf32(pk[r].y);
            w.z = f2tf32(pk[r].z); w.w = f2tf32(pk[r].w);
            *(uint4*)&Ks[(krow0 + (r << 4)) * FLDA + kcg] = w;
            const int d = (vd0 + (r << 2)) << 2;
            Vt[(d + 0) * FLDA + vkv] = f2tf32(pv[r].x);
            Vt[(d + 1) * FLDA + vkv] = f2tf32(pv[r].y);
            Vt[(d + 2) * FLDA + vkv] = f2tf32(pv[r].z);
            Vt[(d + 3) * FLDA + vkv] = f2tf32(pv[r].w);
        }
        if (t + 1 < SEQN / 64) {
            const int n1 = (t + 1) << 6;
            #pragma unroll
            for (int r = 0; r < 4; r++) {
                pk[r] = *(const float4*)&K[(size_t)(n1 + krow0 + (r << 4)) * DM + col0 + kcg];
                pv[r] = *(const float4*)&V[(size_t)(n1 + vkv) * DM + col0 + ((vd0 + (r << 2)) << 2)];
            }
        }
        __syncthreads();

        // ---- S = Qs @ K^T ----
        float sc[8][4];
        #pragma unroll
        for (int j = 0; j < 8; j++)
            #pragma unroll
            for (int q = 0; q < 4; q++) sc[j][q] = 0.f;
        #pragma unroll
        for (int ks = 0; ks < 8; ks++) {
            const int ck = ks << 3;
            #pragma unroll
            for (int jj = 0; jj < 4; jj++) {
                uint32_t b[4];
                const uint32_t baddr =
                    sKs + (uint32_t)((((jj << 4) + lrow) * FLDA + ck + lcol4) << 2);
                ldsm_x4(b, baddr);
                uint32_t bf0[2] = {b[0], b[2]}, bf1[2] = {b[1], b[3]};
                mma_tf32(sc[(jj << 1) + 0], qf[ks], bf0);
                mma_tf32(sc[(jj << 1) + 1], qf[ks], bf1);
            }
        }

        // ---- Online softmax (rows lr and lr+8, quad reduction) ----
        float mx0 = -1e30f, mx1 = -1e30f;
        #pragma unroll
        for (int j = 0; j < 8; j++) {
            mx0 = fmaxf(mx0, fmaxf(sc[j][0], sc[j][1]));
            mx1 = fmaxf(mx1, fmaxf(sc[j][2], sc[j][3]));
        }
        mx0 = fmaxf(mx0, __shfl_xor_sync(0xffffffffu, mx0, 1));
        mx0 = fmaxf(mx0, __shfl_xor_sync(0xffffffffu, mx0, 2));
        mx1 = fmaxf(mx1, __shfl_xor_sync(0xffffffffu, mx1, 1));
        mx1 = fmaxf(mx1, __shfl_xor_sync(0xffffffffu, mx1, 2));
        const float m0n = fmaxf(m0, mx0), m1n = fmaxf(m1, mx1);
        const float c0 = __expf(m0 - m0n), c1 = __expf(m1 - m1n);
        m0 = m0n; m1 = m1n;
        float s0 = 0.f, s1 = 0.f;
        #pragma unroll
        for (int j = 0; j < 8; j++) {
            sc[j][0] = __expf(sc[j][0] - m0n);
            sc[j][1] = __expf(sc[j][1] - m0n);
            sc[j][2] = __expf(sc[j][2] - m1n);
            sc[j][3] = __expf(sc[j][3] - m1n);
            s0 += sc[j][0] + sc[j][1];
            s1 += sc[j][2] + sc[j][3];
        }
        s0 += __shfl_xor_sync(0xffffffffu, s0, 1);
        s0 += __shfl_xor_sync(0xffffffffu, s0, 2);
        s1 += __shfl_xor_sync(0xffffffffu, s1, 1);
        s1 += __shfl_xor_sync(0xffffffffu, s1, 2);
        l0 = l0 * c0 + s0; l1 = l1 * c1 + s1;
        #pragma unroll
        for (int j = 0; j < 8; j++) {
            of[j][0] *= c0; of[j][1] *= c0;
            of[j][2] *= c1; of[j][3] *= c1;
        }
        // ---- P -> smem (tf32) ----
        {
            const int r0 = (wid << 4) + lr;
            #pragma unroll
            for (int j = 0; j < 8; j++) {
                const int cc = (j << 3) + (lc << 1);
                uint2 p0, p1;
                p0.x = f2tf32(sc[j][0]); p0.y = f2tf32(sc[j][1]);
                p1.x = f2tf32(sc[j][2]); p1.y = f2tf32(sc[j][3]);
                *(uint2*)&Ps[r0 * FLDA + cc] = p0;
                *(uint2*)&Ps[(r0 + 8) * FLDA + cc] = p1;
            }
        }
        __syncwarp();   // warp-local: PV reads only this warp's 16 P rows

        // ---- O += P @ V ----
        #pragma unroll
        for (int ks = 0; ks < 8; ks++) {
            const int ck = ks << 3;
            uint32_t af[4];
            const uint32_t aaddr =
                sPs + (uint32_t)((((wid << 4) + lrow) * FLDA + ck + lcol4) << 2);
            ldsm_x4(af, aaddr);
            #pragma unroll
            for (int jj = 0; jj < 4; jj++) {
                uint32_t b[4];
                const uint32_t baddr =
                    sVt + (uint32_t)((((jj << 4) + lrow) * FLDA + ck + lcol4) << 2);
                ldsm_x4(b, baddr);
                uint32_t bf0[2] = {b[0], b[2]}, bf1[2] = {b[1], b[3]};
                mma_tf32(of[(jj << 1) + 0], af, bf0);
                mma_tf32(of[(jj << 1) + 1], af, bf1);
            }
        }
    }

    // ---- Epilogue: O/l -> X ----
    const float inv0 = 1.0f / l0, inv1 = 1.0f / l1;
    const int r0 = q0 + (wid << 4) + lr;
    #pragma unroll
    for (int j = 0; j < 8; j++) {
        const int cc = col0 + (j << 3) + (lc << 1);
        float2 o;
        o.x = of[j][0] * inv0; o.y = of[j][1] * inv0;
        *(float2*)&X[(size_t)r0 * DM + cc] = o;
        o.x = of[j][2] * inv1; o.y = of[j][3] * inv1;
        *(float2*)&X[(size_t)(r0 + 8) * DM + cc] = o;
    }
}

// ---------------------------------------------------------------------------
extern "C" void kernel_launch(void* const* d_in, const int* in_sizes, int n_in,
                              void* d_out, int out_size)
{
    const float* query = (const float*)d_in[0];
    const float* key   = (const float*)d_in[1];
    const float* value = (const float*)d_in[2];
    const float* Wq    = (const float*)d_in[3];
    const float* bq    = (const float*)d_in[4];
    const float* Wk    = (const float*)d_in[5];
    const float* bk    = (const float*)d_in[6];
    const float* Wv    = (const float*)d_in[7];
    const float* bv    = (const float*)d_in[8];
    const float* Wo    = (const float*)d_in[9];
    const float* bo    = (const float*)d_in[10];
    float* out = (float*)d_out;

    float *Qp, *Kp, *Vp, *Xp;
    cudaGetSymbolAddress((void**)&Qp, g_Q);
    cudaGetSymbolAddress((void**)&Kp, g_K);
    cudaGetSymbolAddress((void**)&Vp, g_V);
    cudaGetSymbolAddress((void**)&Xp, g_X);

    cudaFuncSetAttribute(flash_attn_tc,
                         cudaFuncAttributeMaxDynamicSharedMemorySize, FA_SMEM);

    const dim3 gg(DM / 128, SEQN / 128);   // (8, 32)
    gemm_tc<<<gg, 256>>>(query, Wq, bq, Qp);
    gemm_tc<<<gg, 256>>>(key,   Wk, bk, Kp);
    gemm_tc<<<gg, 256>>>(value, Wv, bv, Vp);
    flash_attn_tc<<<dim3(SEQN / 128, NH), 256, FA_SMEM>>>(Qp, Kp, Vp, Xp);
    gemm_tc<<<gg, 256>>>(Xp, Wo, bo, out);
}